// round 4
// baseline (speedup 1.0000x reference)
#include <cuda_runtime.h>
#include <cstddef>

#define B_  32
#define S_  8192
#define H2_ 256
#define CHUNKS 16
#define SPC (S_ / CHUNKS)      // 512 s-rows per block
#define NBLK (B_ * CHUNKS)     // 512 blocks

// ---- scratch (allocation-free) ----
__device__ float g_u[B_ * H2_];                     // h_d_t @ W
__device__ float g_part[NBLK * (H2_ + 1)];          // per-block partial acc[256] + Z
__device__ float g_invZ[B_];

// ---------------- k0: u[b,e] = sum_d h_d_t[b,d] * W[d,e] ----------------
__global__ void k_u(const float* __restrict__ hd, const float* __restrict__ W) {
    int b = blockIdx.x, e = threadIdx.x;
    __shared__ float sh[H2_];
    sh[e] = hd[b * H2_ + e];
    __syncthreads();
    float acc = 0.f;
#pragma unroll 8
    for (int d = 0; d < H2_; d++) acc += sh[d] * W[d * H2_ + e];
    g_u[b * H2_ + e] = acc;
}

// ---------------- k1: fused scores + accumulation (single h_enc pass) ----------------
__global__ void __launch_bounds__(256, 1) k_main(
    const float* __restrict__ henc,
    const float* __restrict__ mask,
    const float* __restrict__ sums,
    float* __restrict__ alphat_out,   // unnormalized a, scaled later
    float* __restrict__ newsum_out)
{
    int blk = blockIdx.x;
    int b = blk / CHUNKS;
    int chunk = blk % CHUNKS;
    int tid = threadIdx.x;
    int w = tid >> 5;
    int l = tid & 31;

    // u[b] distributed: lane l holds dims [4l,4l+4) and [128+4l,128+4l+4)
    const float4* u4 = reinterpret_cast<const float4*>(g_u + b * H2_);
    float4 u0 = u4[l];
    float4 u1 = u4[l + 32];

    float acc0x = 0.f, acc0y = 0.f, acc0z = 0.f, acc0w = 0.f;
    float acc1x = 0.f, acc1y = 0.f, acc1z = 0.f, acc1w = 0.f;
    float Z = 0.f;

    int s0 = chunk * SPC;
    const float4* base = reinterpret_cast<const float4*>(
        henc + ((size_t)b * S_ + s0) * H2_);

    for (int i = w; i < SPC; i += 8) {
        const float4* row = base + (size_t)i * (H2_ / 4);
        float4 h0 = row[l];          // fully coalesced 512B / warp
        float4 h1 = row[l + 32];

        float dot = h0.x * u0.x + h0.y * u0.y + h0.z * u0.z + h0.w * u0.w
                  + h1.x * u1.x + h1.y * u1.y + h1.z * u1.z + h1.w * u1.w;
#pragma unroll
        for (int o = 16; o; o >>= 1)
            dot += __shfl_xor_sync(0xffffffffu, dot, o);

        int s = s0 + i;
        float se = 0.f, m = 0.f;
        if (l == 0) {
            se = sums[b * S_ + s];
            m  = mask[b * S_ + s];
        }
        se = __shfl_sync(0xffffffffu, se, 0);
        m  = __shfl_sync(0xffffffffu, m, 0);

        float e = expf(dot);
        float a = (e / se) * m;
        if (l == 0) {
            newsum_out[b * S_ + s] = se + e;
            alphat_out[b * S_ + s] = a;   // normalized by Z in k3
        }
        Z += a;
        acc0x += a * h0.x; acc0y += a * h0.y; acc0z += a * h0.z; acc0w += a * h0.w;
        acc1x += a * h1.x; acc1y += a * h1.y; acc1z += a * h1.z; acc1w += a * h1.w;
    }

    // block-level reduction of acc[256] across 8 warps (deterministic order)
    __shared__ float sacc[8][H2_];
    __shared__ float sZ[8];
    float* my = sacc[w];
    my[4 * l + 0] = acc0x; my[4 * l + 1] = acc0y;
    my[4 * l + 2] = acc0z; my[4 * l + 3] = acc0w;
    my[128 + 4 * l + 0] = acc1x; my[128 + 4 * l + 1] = acc1y;
    my[128 + 4 * l + 2] = acc1z; my[128 + 4 * l + 3] = acc1w;
    if (l == 0) sZ[w] = Z;
    __syncthreads();

    float tot = 0.f;
#pragma unroll
    for (int ww = 0; ww < 8; ww++) tot += sacc[ww][tid];
    g_part[blk * (H2_ + 1) + tid] = tot;
    if (tid == 0) {
        float z = 0.f;
#pragma unroll
        for (int ww = 0; ww < 8; ww++) z += sZ[ww];
        g_part[blk * (H2_ + 1) + H2_] = z;
    }
}

// ---------------- k2: reduce chunk partials -> ct_e, invZ ----------------
__global__ void k_reduce(float* __restrict__ ct) {
    int b = blockIdx.x, d = threadIdx.x;
    __shared__ float zsh;
    float acc = 0.f;
#pragma unroll
    for (int c = 0; c < CHUNKS; c++)
        acc += g_part[(b * CHUNKS + c) * (H2_ + 1) + d];
    if (d == 0) {
        float z = 0.f;
#pragma unroll
        for (int c = 0; c < CHUNKS; c++)
            z += g_part[(b * CHUNKS + c) * (H2_ + 1) + H2_];
        zsh = z;
        g_invZ[b] = 1.0f / z;
    }
    __syncthreads();
    ct[b * H2_ + d] = acc / zsh;
}

// ---------------- k3: alphat /= Z[b] (in place) ----------------
__global__ void k_scale(float* __restrict__ alphat) {
    int idx = blockIdx.x * blockDim.x + threadIdx.x;
    if (idx < B_ * S_) alphat[idx] *= g_invZ[idx / S_];
}

extern "C" void kernel_launch(void* const* d_in, const int* in_sizes, int n_in,
                              void* d_out, int out_size)
{
    const float* h_d_t = (const float*)d_in[0];   // (32,256)
    const float* h_enc = (const float*)d_in[1];   // (32,8192,256)
    const float* mask  = (const float*)d_in[2];   // (32,8192)
    const float* sums  = (const float*)d_in[3];   // (32,8192)
    const float* W     = (const float*)d_in[4];   // (256,256)

    float* out      = (float*)d_out;
    float* ct_e     = out;                        // 32*256
    float* alphat   = out + B_ * H2_;             // 32*8192
    float* newsum   = out + B_ * H2_ + B_ * S_;   // 32*8192

    k_u<<<B_, H2_>>>(h_d_t, W);
    k_main<<<NBLK, 256>>>(h_enc, mask, sums, alphat, newsum);
    k_reduce<<<B_, H2_>>>(ct_e);
    k_scale<<<(B_ * S_ + 255) / 256, 256>>>(alphat);
}

// round 5
// speedup vs baseline: 1.4383x; 1.4383x over previous
#include <cuda_runtime.h>
#include <cstddef>

#define B_  32
#define S_  8192
#define H2_ 256
#define CHUNKS 32
#define SPC (S_ / CHUNKS)      // 256 s-rows per block
#define NBLK (B_ * CHUNKS)     // 1024 blocks

// ---- scratch (allocation-free) ----
__device__ float g_u[B_ * H2_];                     // h_d_t @ W
__device__ float g_part[NBLK * (H2_ + 1)];          // per-block partial acc[256] + Z
__device__ float g_invZ[B_];

// ---------------- k0: u[b,e] = sum_d h_d_t[b,d] * W[d,e] ----------------
__global__ void k_u(const float* __restrict__ hd, const float* __restrict__ W) {
    int b = blockIdx.x, e = threadIdx.x;
    __shared__ float sh[H2_];
    sh[e] = hd[b * H2_ + e];
    __syncthreads();
    float acc = 0.f;
#pragma unroll 8
    for (int d = 0; d < H2_; d++) acc += sh[d] * W[d * H2_ + e];
    g_u[b * H2_ + e] = acc;
}

// ---------------- k1: fused scores + accumulation (single h_enc pass) ----------------
__global__ void __launch_bounds__(256) k_main(
    const float* __restrict__ henc,
    const float* __restrict__ mask,
    const float* __restrict__ sums,
    float* __restrict__ alphat_out,   // unnormalized a, scaled later
    float* __restrict__ newsum_out)
{
    int blk = blockIdx.x;
    int b = blk >> 5;            // / CHUNKS
    int chunk = blk & 31;        // % CHUNKS
    int tid = threadIdx.x;
    int w = tid >> 5;
    int l = tid & 31;

    // u[b] distributed: lane l holds dims [4l,4l+4) and [128+4l,128+4l+4)
    const float4* u4 = reinterpret_cast<const float4*>(g_u + b * H2_);
    float4 u0 = u4[l];
    float4 u1 = u4[l + 32];

    float acc0x = 0.f, acc0y = 0.f, acc0z = 0.f, acc0w = 0.f;
    float acc1x = 0.f, acc1y = 0.f, acc1z = 0.f, acc1w = 0.f;
    float Z = 0.f;

    int s0 = chunk * SPC;
    const float4* base = reinterpret_cast<const float4*>(
        henc + ((size_t)b * S_ + s0) * H2_);
    const float* sums_b = sums + b * S_ + s0;
    const float* mask_b = mask + b * S_ + s0;
    float* newsum_b = newsum_out + b * S_ + s0;
    float* alphat_b = alphat_out + b * S_ + s0;

    // 2-row unroll per warp: rows i (A) and i+8 (B) -> MLP=4 LDG.128 per warp
    for (int i = w; i < SPC; i += 16) {
        int j = i + 8;
        const float4* rowA = base + (size_t)i * (H2_ / 4);
        const float4* rowB = base + (size_t)j * (H2_ / 4);
        float4 a0 = __ldcs(rowA + l);
        float4 a1 = __ldcs(rowA + l + 32);
        float4 b0 = __ldcs(rowB + l);
        float4 b1 = __ldcs(rowB + l + 32);

        float dA = a0.x * u0.x + a0.y * u0.y + a0.z * u0.z + a0.w * u0.w
                 + a1.x * u1.x + a1.y * u1.y + a1.z * u1.z + a1.w * u1.w;
        float dB = b0.x * u0.x + b0.y * u0.y + b0.z * u0.z + b0.w * u0.w
                 + b1.x * u1.x + b1.y * u1.y + b1.z * u1.z + b1.w * u1.w;
#pragma unroll
        for (int o = 16; o; o >>= 1) {      // two independent shfl chains overlap
            dA += __shfl_xor_sync(0xffffffffu, dA, o);
            dB += __shfl_xor_sync(0xffffffffu, dB, o);
        }

        float seA = 0.f, mA = 0.f, seB = 0.f, mB = 0.f;
        if (l == 0) {
            seA = sums_b[i]; mA = mask_b[i];
            seB = sums_b[j]; mB = mask_b[j];
        }
        seA = __shfl_sync(0xffffffffu, seA, 0);
        mA  = __shfl_sync(0xffffffffu, mA, 0);
        seB = __shfl_sync(0xffffffffu, seB, 0);
        mB  = __shfl_sync(0xffffffffu, mB, 0);

        float eA = __expf(dA);
        float eB = __expf(dB);
        float aA = (eA / seA) * mA;
        float aB = (eB / seB) * mB;
        if (l == 0) {
            newsum_b[i] = seA + eA;
            alphat_b[i] = aA;            // normalized by Z in k3
            newsum_b[j] = seB + eB;
            alphat_b[j] = aB;
        }
        Z += aA + aB;
        acc0x += aA * a0.x + aB * b0.x;
        acc0y += aA * a0.y + aB * b0.y;
        acc0z += aA * a0.z + aB * b0.z;
        acc0w += aA * a0.w + aB * b0.w;
        acc1x += aA * a1.x + aB * b1.x;
        acc1y += aA * a1.y + aB * b1.y;
        acc1z += aA * a1.z + aB * b1.z;
        acc1w += aA * a1.w + aB * b1.w;
    }

    // block-level reduction of acc[256] across 8 warps (deterministic order)
    __shared__ float sacc[8][H2_];
    __shared__ float sZ[8];
    float* my = sacc[w];
    my[4 * l + 0] = acc0x; my[4 * l + 1] = acc0y;
    my[4 * l + 2] = acc0z; my[4 * l + 3] = acc0w;
    my[128 + 4 * l + 0] = acc1x; my[128 + 4 * l + 1] = acc1y;
    my[128 + 4 * l + 2] = acc1z; my[128 + 4 * l + 3] = acc1w;
    if (l == 0) sZ[w] = Z;
    __syncthreads();

    float tot = 0.f;
#pragma unroll
    for (int ww = 0; ww < 8; ww++) tot += sacc[ww][tid];
    g_part[blk * (H2_ + 1) + tid] = tot;
    if (tid == 0) {
        float z = 0.f;
#pragma unroll
        for (int ww = 0; ww < 8; ww++) z += sZ[ww];
        g_part[blk * (H2_ + 1) + H2_] = z;
    }
}

// ---------------- k2: reduce chunk partials -> ct_e, invZ ----------------
__global__ void k_reduce(float* __restrict__ ct) {
    int b = blockIdx.x, d = threadIdx.x;
    __shared__ float zsh;
    float acc = 0.f;
#pragma unroll
    for (int c = 0; c < CHUNKS; c++)
        acc += g_part[(b * CHUNKS + c) * (H2_ + 1) + d];
    if (d == 0) {
        float z = 0.f;
#pragma unroll
        for (int c = 0; c < CHUNKS; c++)
            z += g_part[(b * CHUNKS + c) * (H2_ + 1) + H2_];
        zsh = z;
        g_invZ[b] = 1.0f / z;
    }
    __syncthreads();
    ct[b * H2_ + d] = acc / zsh;
}

// ---------------- k3: alphat *= invZ[b] (in place, float4) ----------------
__global__ void k_scale(float4* __restrict__ alphat) {
    int idx = blockIdx.x * blockDim.x + threadIdx.x;   // 65536 float4s
    float iz = g_invZ[idx >> 11];                      // 2048 float4s per batch
    float4 v = alphat[idx];
    v.x *= iz; v.y *= iz; v.z *= iz; v.w *= iz;
    alphat[idx] = v;
}

extern "C" void kernel_launch(void* const* d_in, const int* in_sizes, int n_in,
                              void* d_out, int out_size)
{
    const float* h_d_t = (const float*)d_in[0];   // (32,256)
    const float* h_enc = (const float*)d_in[1];   // (32,8192,256)
    const float* mask  = (const float*)d_in[2];   // (32,8192)
    const float* sums  = (const float*)d_in[3];   // (32,8192)
    const float* W     = (const float*)d_in[4];   // (256,256)

    float* out      = (float*)d_out;
    float* ct_e     = out;                        // 32*256
    float* alphat   = out + B_ * H2_;             // 32*8192
    float* newsum   = out + B_ * H2_ + B_ * S_;   // 32*8192

    k_u<<<B_, H2_>>>(h_d_t, W);
    k_main<<<NBLK, 256>>>(h_enc, mask, sums, alphat, newsum);
    k_reduce<<<B_, H2_>>>(ct_e);
    k_scale<<<(B_ * S_ / 4) / 256, 256>>>((float4*)alphat);
}